// round 1
// baseline (speedup 1.0000x reference)
#include <cuda_runtime.h>
#include <cuda_bf16.h>

// ---------------- Problem constants ----------------
#define D_MODEL 768
#define DIM_I   1536          // DI
#define DS      16
#define DC      4
#define DR      48
#define NLAYER  8
#define BATCH   2
#define SEQLEN  512
#define ROWS    (BATCH*SEQLEN)   // 1024
#define VOCAB   32000
#define XW      (DR + 2*DS)      // 80

// ---------------- Scratch (device globals: no allocation allowed) ----------------
__device__ float g_h   [ROWS * D_MODEL];
__device__ float g_hln [ROWS * D_MODEL];
__device__ float g_temb[BATCH * D_MODEL];
__device__ float g_xz  [ROWS * 2 * DIM_I];
__device__ float g_x   [ROWS * DIM_I];
__device__ float g_xdbl[ROWS * XW];
__device__ float g_dt  [ROWS * DIM_I];
__device__ float g_y   [ROWS * DIM_I];

// ---------------- Helpers ----------------
__device__ __forceinline__ float softplusf(float v) {
    return (v > 20.f) ? v : log1pf(__expf(v));
}
__device__ __forceinline__ float siluf(float v) {
    return v / (1.f + __expf(-v));
}

// ---------------- Generic fp32 GEMM: C = A(MxK) @ B(KxN) [+bias] [+epi] ----------------
// BM=BN=64, BK=16, 256 threads, 4x4 micro-tile.
// Assumes: M % 64 == 0 (always true: M=1024), K % 16 == 0 (768/1536/48 ok),
// N % 4 == 0 (3072/80/1536/768/32000 ok). N-edge guarded.
#define BM 64
#define BN 64
#define BKK 16

enum { EPI_NONE = 0, EPI_SOFTPLUS = 1, EPI_ADD = 2 };

template <int EPI>
__global__ __launch_bounds__(256) void sgemm_k(
    const float* __restrict__ A, int lda,
    const float* __restrict__ Bm, int ldb,
    const float* __restrict__ bias,      // nullable, length N
    const float* __restrict__ add,       // residual (same ldc), for EPI_ADD
    float* __restrict__ C, int ldc,
    int N, int K)
{
    __shared__ float As[BKK][BM];
    __shared__ float Bs[BKK][BN];

    const int t  = threadIdx.x;
    const int tx = t & 15;
    const int ty = t >> 4;
    const int m0 = blockIdx.y * BM;
    const int n0 = blockIdx.x * BN;

    // A-tile load mapping: 64 rows x 16 cols, one float4 per thread
    const int arow = t >> 2;          // 0..63
    const int akq  = (t & 3) << 2;    // 0,4,8,12
    // B-tile load mapping: 16 rows x 64 cols, one float4 per thread
    const int bk = t >> 4;            // 0..15
    const int bn = (t & 15) << 2;     // 0..60
    const bool bvalid = (n0 + bn) < N;

    float acc[4][4];
#pragma unroll
    for (int i = 0; i < 4; i++)
#pragma unroll
        for (int j = 0; j < 4; j++) acc[i][j] = 0.f;

    for (int k0 = 0; k0 < K; k0 += BKK) {
        float4 av = *(const float4*)(A + (size_t)(m0 + arow) * lda + k0 + akq);
        As[akq + 0][arow] = av.x;
        As[akq + 1][arow] = av.y;
        As[akq + 2][arow] = av.z;
        As[akq + 3][arow] = av.w;
        float4 bv = bvalid ? *(const float4*)(Bm + (size_t)(k0 + bk) * ldb + n0 + bn)
                           : make_float4(0.f, 0.f, 0.f, 0.f);
        *(float4*)&Bs[bk][bn] = bv;
        __syncthreads();
#pragma unroll
        for (int k = 0; k < BKK; k++) {
            float4 a4 = *(const float4*)&As[k][ty * 4];
            float4 b4 = *(const float4*)&Bs[k][tx * 4];
            float ar[4] = {a4.x, a4.y, a4.z, a4.w};
            float br[4] = {b4.x, b4.y, b4.z, b4.w};
#pragma unroll
            for (int i = 0; i < 4; i++)
#pragma unroll
                for (int j = 0; j < 4; j++)
                    acc[i][j] = fmaf(ar[i], br[j], acc[i][j]);
        }
        __syncthreads();
    }

    const int col = n0 + tx * 4;
    if (col >= N) return;
    float4 bvz = bias ? *(const float4*)(bias + col) : make_float4(0.f, 0.f, 0.f, 0.f);
#pragma unroll
    for (int i = 0; i < 4; i++) {
        const int row = m0 + ty * 4 + i;
        float4 o;
        o.x = acc[i][0] + bvz.x;
        o.y = acc[i][1] + bvz.y;
        o.z = acc[i][2] + bvz.z;
        o.w = acc[i][3] + bvz.w;
        if (EPI == EPI_SOFTPLUS) {
            o.x = softplusf(o.x); o.y = softplusf(o.y);
            o.z = softplusf(o.z); o.w = softplusf(o.w);
        } else if (EPI == EPI_ADD) {
            float4 r = *(const float4*)(add + (size_t)row * ldc + col);
            o.x += r.x; o.y += r.y; o.z += r.z; o.w += r.w;
        }
        *(float4*)(C + (size_t)row * ldc + col) = o;
    }
}

// ---------------- Embedding gather ----------------
__global__ void embed_kernel(const int* __restrict__ ids,
                             const float* __restrict__ emb,
                             float* __restrict__ h)
{
    const int row = blockIdx.x;
    const int id  = ids[row];
    const float4* src = (const float4*)(emb + (size_t)id * D_MODEL);
    float4* dst = (float4*)(h + (size_t)row * D_MODEL);
    dst[threadIdx.x] = src[threadIdx.x];
}

// ---------------- Time embedding: t_emb = silu(t*tw1+tb1) @ tw2 + tb2 ----------------
__global__ __launch_bounds__(128) void temb_kernel(
    const float* __restrict__ tn, const float* __restrict__ tw1,
    const float* __restrict__ tb1, const float* __restrict__ tw2,
    const float* __restrict__ tb2, float* __restrict__ temb)
{
    __shared__ float u[D_MODEL];
    const int b = blockIdx.y;
    const float tv = tn[b];
    for (int dd = threadIdx.x; dd < D_MODEL; dd += 128) {
        float v = fmaf(tv, tw1[dd], tb1[dd]);
        u[dd] = siluf(v);
    }
    __syncthreads();
    const int d2 = blockIdx.x * 128 + threadIdx.x;
    float acc = tb2[d2];
    for (int dd = 0; dd < D_MODEL; dd++)
        acc = fmaf(u[dd], tw2[dd * D_MODEL + d2], acc);
    temb[b * D_MODEL + d2] = acc;
}

// ---------------- LayerNorm: o = LN(x [+ temb_b]) * g + b ----------------
__global__ __launch_bounds__(256) void ln_kernel(
    const float* __restrict__ x, const float* __restrict__ temb,
    const float* __restrict__ g, const float* __restrict__ bb,
    float* __restrict__ o)
{
    const int row = blockIdx.x;
    const int batch = row >> 9;   // / SEQLEN
    const float* xr = x + (size_t)row * D_MODEL;
    const float* tr = temb ? temb + batch * D_MODEL : nullptr;

    float v[3];
    float s = 0.f, sq = 0.f;
#pragma unroll
    for (int i = 0; i < 3; i++) {
        const int d = threadIdx.x + i * 256;
        float vv = xr[d];
        if (tr) vv += tr[d];
        v[i] = vv;
        s += vv;
        sq += vv * vv;
    }
#pragma unroll
    for (int off = 16; off; off >>= 1) {
        s  += __shfl_xor_sync(0xffffffffu, s,  off);
        sq += __shfl_xor_sync(0xffffffffu, sq, off);
    }
    __shared__ float rs[8], rq[8];
    const int warp = threadIdx.x >> 5, lane = threadIdx.x & 31;
    if (lane == 0) { rs[warp] = s; rq[warp] = sq; }
    __syncthreads();
    if (threadIdx.x == 0) {
        float a = 0.f, b2 = 0.f;
#pragma unroll
        for (int w = 0; w < 8; w++) { a += rs[w]; b2 += rq[w]; }
        rs[0] = a; rq[0] = b2;
    }
    __syncthreads();
    const float mean = rs[0] * (1.f / D_MODEL);
    const float var  = rq[0] * (1.f / D_MODEL) - mean * mean;
    const float rstd = rsqrtf(var + 1e-5f);
#pragma unroll
    for (int i = 0; i < 3; i++) {
        const int d = threadIdx.x + i * 256;
        o[(size_t)row * D_MODEL + d] = (v[i] - mean) * rstd * g[d] + bb[d];
    }
}

// ---------------- Causal depthwise conv (DC=4) + bias + silu ----------------
__global__ __launch_bounds__(256) void conv_silu_kernel(
    const float* __restrict__ xz, const float* __restrict__ cw,
    const float* __restrict__ cb, float* __restrict__ x)
{
    const int idx = blockIdx.x * 256 + threadIdx.x;   // over ROWS*DIM_I
    const int c   = idx % DIM_I;
    const int row = idx / DIM_I;
    const int l   = row & (SEQLEN - 1);
    const int b   = row >> 9;
    const float w0 = cw[c * DC + 0], w1 = cw[c * DC + 1];
    const float w2 = cw[c * DC + 2], w3 = cw[c * DC + 3];
    float acc = cb[c];
    const float* base = xz + ((size_t)b * SEQLEN) * (2 * DIM_I) + c;
    if (l - 3 >= 0) acc = fmaf(base[(size_t)(l - 3) * (2 * DIM_I)], w0, acc);
    if (l - 2 >= 0) acc = fmaf(base[(size_t)(l - 2) * (2 * DIM_I)], w1, acc);
    if (l - 1 >= 0) acc = fmaf(base[(size_t)(l - 1) * (2 * DIM_I)], w2, acc);
    acc = fmaf(base[(size_t)l * (2 * DIM_I)], w3, acc);
    x[(size_t)row * DIM_I + c] = siluf(acc);
}

// ---------------- Selective scan (sequential over L), fused y epilogue ----------------
// y[b,l,d] = (sum_k s_k*C_k + Dp*x) * silu(z)
__global__ __launch_bounds__(128) void scan_kernel(
    const float* __restrict__ dt, const float* __restrict__ x,
    const float* __restrict__ xz, const float* __restrict__ xdbl,
    const float* __restrict__ Alog, const float* __restrict__ Dp,
    float* __restrict__ y)
{
    const int d = blockIdx.x * 128 + threadIdx.x;
    const int b = blockIdx.y;

    float A[DS], s[DS];
#pragma unroll
    for (int k = 0; k < DS; k++) {
        A[k] = -expf(Alog[(size_t)d * DS + k]);
        s[k] = 0.f;
    }
    const float dpv = Dp[d];
    const int base = b * SEQLEN;

    for (int tt = 0; tt < SEQLEN; tt++) {
        const int row = base + tt;
        const float dtv = dt[(size_t)row * DIM_I + d];
        const float xv  = x [(size_t)row * DIM_I + d];
        const float zv  = xz[(size_t)row * 2 * DIM_I + DIM_I + d];
        const float4* q = (const float4*)(xdbl + (size_t)row * XW + DR);
        float4 b0 = q[0], b1 = q[1], b2 = q[2], b3 = q[3];
        float4 c0 = q[4], c1 = q[5], c2 = q[6], c3 = q[7];
        const float Bv[DS] = {b0.x,b0.y,b0.z,b0.w, b1.x,b1.y,b1.z,b1.w,
                              b2.x,b2.y,b2.z,b2.w, b3.x,b3.y,b3.z,b3.w};
        const float Cv[DS] = {c0.x,c0.y,c0.z,c0.w, c1.x,c1.y,c1.z,c1.w,
                              c2.x,c2.y,c2.z,c2.w, c3.x,c3.y,c3.z,c3.w};
        const float dx = dtv * xv;
        float acc = 0.f;
#pragma unroll
        for (int k = 0; k < DS; k++) {
            s[k] = fmaf(s[k], __expf(dtv * A[k]), dx * Bv[k]);
            acc  = fmaf(s[k], Cv[k], acc);
        }
        float yv = acc + dpv * xv;
        yv *= zv / (1.f + __expf(-zv));
        y[(size_t)row * DIM_I + d] = yv;
    }
}

// ---------------- Launch ----------------
extern "C" void kernel_launch(void* const* d_in, const int* in_sizes, int n_in,
                              void* d_out, int out_size)
{
    (void)in_sizes; (void)n_in; (void)out_size;
    const int*   ids     = (const int*)  d_in[0];
    const float* t_norm  = (const float*)d_in[1];
    const float* tok_emb = (const float*)d_in[2];
    const float* tw1     = (const float*)d_in[3];
    const float* tb1     = (const float*)d_in[4];
    const float* tw2     = (const float*)d_in[5];
    const float* tb2     = (const float*)d_in[6];
    const float* ln_g    = (const float*)d_in[7];
    const float* ln_b    = (const float*)d_in[8];
    const float* W_in    = (const float*)d_in[9];
    const float* b_in    = (const float*)d_in[10];
    const float* conv_w  = (const float*)d_in[11];
    const float* conv_b  = (const float*)d_in[12];
    const float* W_x     = (const float*)d_in[13];
    const float* W_dt    = (const float*)d_in[14];
    const float* b_dt    = (const float*)d_in[15];
    const float* A_log   = (const float*)d_in[16];
    const float* D_p     = (const float*)d_in[17];
    const float* W_out   = (const float*)d_in[18];
    const float* b_out   = (const float*)d_in[19];
    const float* fn_g    = (const float*)d_in[20];
    const float* fn_b    = (const float*)d_in[21];
    const float* W_head  = (const float*)d_in[22];
    const float* b_head  = (const float*)d_in[23];
    float* out = (float*)d_out;

    float *h, *hln, *temb, *xz, *x, *xdbl, *dtb, *y;
    cudaGetSymbolAddress((void**)&h,    g_h);
    cudaGetSymbolAddress((void**)&hln,  g_hln);
    cudaGetSymbolAddress((void**)&temb, g_temb);
    cudaGetSymbolAddress((void**)&xz,   g_xz);
    cudaGetSymbolAddress((void**)&x,    g_x);
    cudaGetSymbolAddress((void**)&xdbl, g_xdbl);
    cudaGetSymbolAddress((void**)&dtb,  g_dt);
    cudaGetSymbolAddress((void**)&y,    g_y);

    embed_kernel<<<ROWS, D_MODEL / 4>>>(ids, tok_emb, h);
    temb_kernel<<<dim3(D_MODEL / 128, BATCH), 128>>>(t_norm, tw1, tb1, tw2, tb2, temb);

    for (int l = 0; l < NLAYER; l++) {
        ln_kernel<<<ROWS, 256>>>(h, temb, ln_g + l * D_MODEL, ln_b + l * D_MODEL, hln);

        // xz = hln @ W_in + b_in         (1024 x 3072, K=768)
        sgemm_k<EPI_NONE><<<dim3(2 * DIM_I / BN, ROWS / BM), 256>>>(
            hln, D_MODEL, W_in + (size_t)l * D_MODEL * 2 * DIM_I, 2 * DIM_I,
            b_in + l * 2 * DIM_I, nullptr, xz, 2 * DIM_I, 2 * DIM_I, D_MODEL);

        conv_silu_kernel<<<ROWS * DIM_I / 256, 256>>>(
            xz, conv_w + l * DIM_I * DC, conv_b + l * DIM_I, x);

        // xdbl = x @ W_x                  (1024 x 80, K=1536)
        sgemm_k<EPI_NONE><<<dim3((XW + BN - 1) / BN, ROWS / BM), 256>>>(
            x, DIM_I, W_x + (size_t)l * DIM_I * XW, XW,
            nullptr, nullptr, xdbl, XW, XW, DIM_I);

        // dt = softplus(xdbl[:, :48] @ W_dt + b_dt)   (1024 x 1536, K=48)
        sgemm_k<EPI_SOFTPLUS><<<dim3(DIM_I / BN, ROWS / BM), 256>>>(
            xdbl, XW, W_dt + (size_t)l * DR * DIM_I, DIM_I,
            b_dt + l * DIM_I, nullptr, dtb, DIM_I, DIM_I, DR);

        scan_kernel<<<dim3(DIM_I / 128, BATCH), 128>>>(
            dtb, x, xz, xdbl, A_log + (size_t)l * DIM_I * DS, D_p + l * DIM_I, y);

        // h = hln + y @ W_out + b_out     (1024 x 768, K=1536)
        sgemm_k<EPI_ADD><<<dim3(D_MODEL / BN, ROWS / BM), 256>>>(
            y, DIM_I, W_out + (size_t)l * DIM_I * D_MODEL, D_MODEL,
            b_out + l * D_MODEL, hln, h, D_MODEL, D_MODEL, DIM_I);
    }

    ln_kernel<<<ROWS, 256>>>(h, nullptr, fn_g, fn_b, hln);

    // logits = hln @ W_head + b_head     (1024 x 32000, K=768)
    sgemm_k<EPI_NONE><<<dim3(VOCAB / BN, ROWS / BM), 256>>>(
        hln, D_MODEL, W_head, VOCAB, b_head, nullptr, out, VOCAB, VOCAB, D_MODEL);
}

// round 2
// speedup vs baseline: 1.2636x; 1.2636x over previous
#include <cuda_runtime.h>
#include <cuda_bf16.h>

// ---------------- Problem constants ----------------
#define D_MODEL 768
#define DIM_I   1536          // DI
#define DS      16
#define DC      4
#define DR      48
#define NLAYER  8
#define BATCH   2
#define SEQLEN  512
#define ROWS    (BATCH*SEQLEN)   // 1024
#define VOCAB   32000
#define XW      (DR + 2*DS)      // 80

// ---------------- Scratch (device globals: no allocation allowed) ----------------
__device__ float g_h   [ROWS * D_MODEL];
__device__ float g_hln [ROWS * D_MODEL];
__device__ float g_temb[BATCH * D_MODEL];
__device__ float g_xz  [ROWS * 2 * DIM_I];
__device__ float g_x   [ROWS * DIM_I];
__device__ float g_xdbl[ROWS * XW];
__device__ float g_dt  [ROWS * DIM_I];
__device__ float g_y   [ROWS * DIM_I];

// ---------------- Helpers ----------------
__device__ __forceinline__ float softplusf(float v) {
    return (v > 20.f) ? v : log1pf(__expf(v));
}
__device__ __forceinline__ float siluf(float v) {
    return v / (1.f + __expf(-v));
}

// ---------------- Generic fp32 GEMM: C = A(MxK) @ B(KxN) [+bias] [+epi] ----------------
#define BM 64
#define BN 64
#define BKK 16

enum { EPI_NONE = 0, EPI_SOFTPLUS = 1, EPI_ADD = 2 };

template <int EPI>
__global__ __launch_bounds__(256) void sgemm_k(
    const float* __restrict__ A, int lda,
    const float* __restrict__ Bm, int ldb,
    const float* __restrict__ bias,      // nullable, length N
    const float* __restrict__ add,       // residual (same ldc), for EPI_ADD
    float* __restrict__ C, int ldc,
    int N, int K)
{
    __shared__ float As[BKK][BM];
    __shared__ float Bs[BKK][BN];

    const int t  = threadIdx.x;
    const int tx = t & 15;
    const int ty = t >> 4;
    const int m0 = blockIdx.y * BM;
    const int n0 = blockIdx.x * BN;

    const int arow = t >> 2;          // 0..63
    const int akq  = (t & 3) << 2;    // 0,4,8,12
    const int bk = t >> 4;            // 0..15
    const int bn = (t & 15) << 2;     // 0..60
    const bool bvalid = (n0 + bn) < N;

    float acc[4][4];
#pragma unroll
    for (int i = 0; i < 4; i++)
#pragma unroll
        for (int j = 0; j < 4; j++) acc[i][j] = 0.f;

    for (int k0 = 0; k0 < K; k0 += BKK) {
        float4 av = *(const float4*)(A + (size_t)(m0 + arow) * lda + k0 + akq);
        As[akq + 0][arow] = av.x;
        As[akq + 1][arow] = av.y;
        As[akq + 2][arow] = av.z;
        As[akq + 3][arow] = av.w;
        float4 bv = bvalid ? *(const float4*)(Bm + (size_t)(k0 + bk) * ldb + n0 + bn)
                           : make_float4(0.f, 0.f, 0.f, 0.f);
        *(float4*)&Bs[bk][bn] = bv;
        __syncthreads();
#pragma unroll
        for (int k = 0; k < BKK; k++) {
            float4 a4 = *(const float4*)&As[k][ty * 4];
            float4 b4 = *(const float4*)&Bs[k][tx * 4];
            float ar[4] = {a4.x, a4.y, a4.z, a4.w};
            float br[4] = {b4.x, b4.y, b4.z, b4.w};
#pragma unroll
            for (int i = 0; i < 4; i++)
#pragma unroll
                for (int j = 0; j < 4; j++)
                    acc[i][j] = fmaf(ar[i], br[j], acc[i][j]);
        }
        __syncthreads();
    }

    const int col = n0 + tx * 4;
    if (col >= N) return;
    float4 bvz = bias ? *(const float4*)(bias + col) : make_float4(0.f, 0.f, 0.f, 0.f);
#pragma unroll
    for (int i = 0; i < 4; i++) {
        const int row = m0 + ty * 4 + i;
        float4 o;
        o.x = acc[i][0] + bvz.x;
        o.y = acc[i][1] + bvz.y;
        o.z = acc[i][2] + bvz.z;
        o.w = acc[i][3] + bvz.w;
        if (EPI == EPI_SOFTPLUS) {
            o.x = softplusf(o.x); o.y = softplusf(o.y);
            o.z = softplusf(o.z); o.w = softplusf(o.w);
        } else if (EPI == EPI_ADD) {
            float4 r = *(const float4*)(add + (size_t)row * ldc + col);
            o.x += r.x; o.y += r.y; o.z += r.z; o.w += r.w;
        }
        *(float4*)(C + (size_t)row * ldc + col) = o;
    }
}

// ---------------- Embedding gather ----------------
__global__ void embed_kernel(const int* __restrict__ ids,
                             const float* __restrict__ emb,
                             float* __restrict__ h)
{
    const int row = blockIdx.x;
    const int id  = ids[row];
    const float4* src = (const float4*)(emb + (size_t)id * D_MODEL);
    float4* dst = (float4*)(h + (size_t)row * D_MODEL);
    dst[threadIdx.x] = src[threadIdx.x];
}

// ---------------- Time embedding: t_emb = silu(t*tw1+tb1) @ tw2 + tb2 ----------------
__global__ __launch_bounds__(128) void temb_kernel(
    const float* __restrict__ tn, const float* __restrict__ tw1,
    const float* __restrict__ tb1, const float* __restrict__ tw2,
    const float* __restrict__ tb2, float* __restrict__ temb)
{
    __shared__ float u[D_MODEL];
    const int b = blockIdx.y;
    const float tv = tn[b];
    for (int dd = threadIdx.x; dd < D_MODEL; dd += 128) {
        float v = fmaf(tv, tw1[dd], tb1[dd]);
        u[dd] = siluf(v);
    }
    __syncthreads();
    const int d2 = blockIdx.x * 128 + threadIdx.x;
    float acc = tb2[d2];
    for (int dd = 0; dd < D_MODEL; dd++)
        acc = fmaf(u[dd], tw2[dd * D_MODEL + d2], acc);
    temb[b * D_MODEL + d2] = acc;
}

// ---------------- LayerNorm: o = LN(x [+ temb_b]) * g + b ----------------
__global__ __launch_bounds__(256) void ln_kernel(
    const float* __restrict__ x, const float* __restrict__ temb,
    const float* __restrict__ g, const float* __restrict__ bb,
    float* __restrict__ o)
{
    const int row = blockIdx.x;
    const int batch = row >> 9;   // / SEQLEN
    const float* xr = x + (size_t)row * D_MODEL;
    const float* tr = temb ? temb + batch * D_MODEL : nullptr;

    float v[3];
    float s = 0.f, sq = 0.f;
#pragma unroll
    for (int i = 0; i < 3; i++) {
        const int d = threadIdx.x + i * 256;
        float vv = xr[d];
        if (tr) vv += tr[d];
        v[i] = vv;
        s += vv;
        sq += vv * vv;
    }
#pragma unroll
    for (int off = 16; off; off >>= 1) {
        s  += __shfl_xor_sync(0xffffffffu, s,  off);
        sq += __shfl_xor_sync(0xffffffffu, sq, off);
    }
    __shared__ float rs[8], rq[8];
    const int warp = threadIdx.x >> 5, lane = threadIdx.x & 31;
    if (lane == 0) { rs[warp] = s; rq[warp] = sq; }
    __syncthreads();
    if (threadIdx.x == 0) {
        float a = 0.f, b2 = 0.f;
#pragma unroll
        for (int w = 0; w < 8; w++) { a += rs[w]; b2 += rq[w]; }
        rs[0] = a; rq[0] = b2;
    }
    __syncthreads();
    const float mean = rs[0] * (1.f / D_MODEL);
    const float var  = rq[0] * (1.f / D_MODEL) - mean * mean;
    const float rstd = rsqrtf(var + 1e-5f);
#pragma unroll
    for (int i = 0; i < 3; i++) {
        const int d = threadIdx.x + i * 256;
        o[(size_t)row * D_MODEL + d] = (v[i] - mean) * rstd * g[d] + bb[d];
    }
}

// ---------------- Causal depthwise conv (DC=4) + bias + silu ----------------
__global__ __launch_bounds__(256) void conv_silu_kernel(
    const float* __restrict__ xz, const float* __restrict__ cw,
    const float* __restrict__ cb, float* __restrict__ x)
{
    const int idx = blockIdx.x * 256 + threadIdx.x;   // over ROWS*DIM_I
    const int c   = idx % DIM_I;
    const int row = idx / DIM_I;
    const int l   = row & (SEQLEN - 1);
    const int b   = row >> 9;
    const float w0 = cw[c * DC + 0], w1 = cw[c * DC + 1];
    const float w2 = cw[c * DC + 2], w3 = cw[c * DC + 3];
    float acc = cb[c];
    const float* base = xz + ((size_t)b * SEQLEN) * (2 * DIM_I) + c;
    if (l - 3 >= 0) acc = fmaf(base[(size_t)(l - 3) * (2 * DIM_I)], w0, acc);
    if (l - 2 >= 0) acc = fmaf(base[(size_t)(l - 2) * (2 * DIM_I)], w1, acc);
    if (l - 1 >= 0) acc = fmaf(base[(size_t)(l - 1) * (2 * DIM_I)], w2, acc);
    acc = fmaf(base[(size_t)l * (2 * DIM_I)], w3, acc);
    x[(size_t)row * DIM_I + c] = siluf(acc);
}

// ---------------- Selective scan v2: state-parallel + software pipelined ----------------
// Thread layout: blockDim=128 = 16 d-lanes x 8 k-threads. Each thread owns
// states k and k+8 of one (b,d) lane. Output reduced over the 8 k-threads via
// shfl_xor (groups of 8 lanes are warp-aligned). Grid: (DIM_I/16, BATCH) = 192 blocks.
// Per-step loads for t+1 are prefetched while computing step t, so the serial
// dependency per step is a single FFMA on the state.
__global__ __launch_bounds__(128) void scan_kernel(
    const float* __restrict__ dt, const float* __restrict__ x,
    const float* __restrict__ xz, const float* __restrict__ xdbl,
    const float* __restrict__ Alog, const float* __restrict__ Dp,
    float* __restrict__ y)
{
    const int dl = threadIdx.x >> 3;         // 0..15
    const int kt = threadIdx.x & 7;          // 0..7
    const int d  = blockIdx.x * 16 + dl;
    const int b  = blockIdx.y;
    const int k1 = kt, k2 = kt + 8;

    const float A1 = -expf(Alog[(size_t)d * DS + k1]);
    const float A2 = -expf(Alog[(size_t)d * DS + k2]);
    const float dpv = Dp[d];

    float s1 = 0.f, s2 = 0.f;
    const int base = b * SEQLEN;

    // prefetch t = 0
    const float* dtp = dt + (size_t)base * DIM_I + d;
    const float* xp  = x  + (size_t)base * DIM_I + d;
    const float* zp  = xz + (size_t)base * 2 * DIM_I + DIM_I + d;
    const float* qp  = xdbl + (size_t)base * XW + DR;

    float dtv = dtp[0];
    float xv  = xp[0];
    float zv  = zp[0];
    float b1v = qp[k1], b2v = qp[k2];
    float c1v = qp[DS + k1], c2v = qp[DS + k2];

    for (int tt = 0; tt < SEQLEN; tt++) {
        // prefetch t+1 (independent of state chain)
        float ndt = dtv, nx = xv, nz = zv, nb1 = b1v, nb2 = b2v, nc1 = c1v, nc2 = c2v;
        if (tt + 1 < SEQLEN) {
            const size_t r1 = (size_t)(tt + 1);
            ndt = dtp[r1 * DIM_I];
            nx  = xp [r1 * DIM_I];
            nz  = zp [r1 * 2 * DIM_I];
            const float* q = qp + r1 * XW;
            nb1 = q[k1]; nb2 = q[k2];
            nc1 = q[DS + k1]; nc2 = q[DS + k2];
        }

        // compute step t
        const float dx = dtv * xv;
        const float e1 = __expf(dtv * A1);
        const float e2 = __expf(dtv * A2);
        s1 = fmaf(s1, e1, dx * b1v);
        s2 = fmaf(s2, e2, dx * b2v);
        float p = fmaf(s2, c2v, s1 * c1v);
        p += __shfl_xor_sync(0xffffffffu, p, 1);
        p += __shfl_xor_sync(0xffffffffu, p, 2);
        p += __shfl_xor_sync(0xffffffffu, p, 4);
        if (kt == 0) {
            float yv = fmaf(dpv, xv, p);
            yv *= zv / (1.f + __expf(-zv));
            y[(size_t)(base + tt) * DIM_I + d] = yv;
        }

        dtv = ndt; xv = nx; zv = nz;
        b1v = nb1; b2v = nb2; c1v = nc1; c2v = nc2;
    }
}

// ---------------- Launch ----------------
extern "C" void kernel_launch(void* const* d_in, const int* in_sizes, int n_in,
                              void* d_out, int out_size)
{
    (void)in_sizes; (void)n_in; (void)out_size;
    const int*   ids     = (const int*)  d_in[0];
    const float* t_norm  = (const float*)d_in[1];
    const float* tok_emb = (const float*)d_in[2];
    const float* tw1     = (const float*)d_in[3];
    const float* tb1     = (const float*)d_in[4];
    const float* tw2     = (const float*)d_in[5];
    const float* tb2     = (const float*)d_in[6];
    const float* ln_g    = (const float*)d_in[7];
    const float* ln_b    = (const float*)d_in[8];
    const float* W_in    = (const float*)d_in[9];
    const float* b_in    = (const float*)d_in[10];
    const float* conv_w  = (const float*)d_in[11];
    const float* conv_b  = (const float*)d_in[12];
    const float* W_x     = (const float*)d_in[13];
    const float* W_dt    = (const float*)d_in[14];
    const float* b_dt    = (const float*)d_in[15];
    const float* A_log   = (const float*)d_in[16];
    const float* D_p     = (const float*)d_in[17];
    const float* W_out   = (const float*)d_in[18];
    const float* b_out   = (const float*)d_in[19];
    const float* fn_g    = (const float*)d_in[20];
    const float* fn_b    = (const float*)d_in[21];
    const float* W_head  = (const float*)d_in[22];
    const float* b_head  = (const float*)d_in[23];
    float* out = (float*)d_out;

    float *h, *hln, *temb, *xz, *x, *xdbl, *dtb, *y;
    cudaGetSymbolAddress((void**)&h,    g_h);
    cudaGetSymbolAddress((void**)&hln,  g_hln);
    cudaGetSymbolAddress((void**)&temb, g_temb);
    cudaGetSymbolAddress((void**)&xz,   g_xz);
    cudaGetSymbolAddress((void**)&x,    g_x);
    cudaGetSymbolAddress((void**)&xdbl, g_xdbl);
    cudaGetSymbolAddress((void**)&dtb,  g_dt);
    cudaGetSymbolAddress((void**)&y,    g_y);

    embed_kernel<<<ROWS, D_MODEL / 4>>>(ids, tok_emb, h);
    temb_kernel<<<dim3(D_MODEL / 128, BATCH), 128>>>(t_norm, tw1, tb1, tw2, tb2, temb);

    for (int l = 0; l < NLAYER; l++) {
        ln_kernel<<<ROWS, 256>>>(h, temb, ln_g + l * D_MODEL, ln_b + l * D_MODEL, hln);

        // xz = hln @ W_in + b_in         (1024 x 3072, K=768)
        sgemm_k<EPI_NONE><<<dim3(2 * DIM_I / BN, ROWS / BM), 256>>>(
            hln, D_MODEL, W_in + (size_t)l * D_MODEL * 2 * DIM_I, 2 * DIM_I,
            b_in + l * 2 * DIM_I, nullptr, xz, 2 * DIM_I, 2 * DIM_I, D_MODEL);

        conv_silu_kernel<<<ROWS * DIM_I / 256, 256>>>(
            xz, conv_w + l * DIM_I * DC, conv_b + l * DIM_I, x);

        // xdbl = x @ W_x                  (1024 x 80, K=1536)
        sgemm_k<EPI_NONE><<<dim3((XW + BN - 1) / BN, ROWS / BM), 256>>>(
            x, DIM_I, W_x + (size_t)l * DIM_I * XW, XW,
            nullptr, nullptr, xdbl, XW, XW, DIM_I);

        // dt = softplus(xdbl[:, :48] @ W_dt + b_dt)   (1024 x 1536, K=48)
        sgemm_k<EPI_SOFTPLUS><<<dim3(DIM_I / BN, ROWS / BM), 256>>>(
            xdbl, XW, W_dt + (size_t)l * DR * DIM_I, DIM_I,
            b_dt + l * DIM_I, nullptr, dtb, DIM_I, DIM_I, DR);

        scan_kernel<<<dim3(DIM_I / 16, BATCH), 128>>>(
            dtb, x, xz, xdbl, A_log + (size_t)l * DIM_I * DS, D_p + l * DIM_I, y);

        // h = hln + y @ W_out + b_out     (1024 x 768, K=1536)
        sgemm_k<EPI_ADD><<<dim3(D_MODEL / BN, ROWS / BM), 256>>>(
            y, DIM_I, W_out + (size_t)l * DIM_I * D_MODEL, D_MODEL,
            b_out + l * D_MODEL, hln, h, D_MODEL, D_MODEL, DIM_I);
    }

    ln_kernel<<<ROWS, 256>>>(h, nullptr, fn_g, fn_b, hln);

    // logits = hln @ W_head + b_head     (1024 x 32000, K=768)
    sgemm_k<EPI_NONE><<<dim3(VOCAB / BN, ROWS / BM), 256>>>(
        hln, D_MODEL, W_head, VOCAB, b_head, nullptr, out, VOCAB, VOCAB, D_MODEL);
}